// round 2
// baseline (speedup 1.0000x reference)
#include <cuda_runtime.h>
#include <math.h>
#include <stdint.h>

// ---------------------------------------------------------------------------
// RSSM scan: T=50, B=2048
// Per step:
//   rnn_in = relu([post_state|a_t] @ W_sa^T + b_sa)          [B,1024] K=288
//   gi = rnn_in @ W_ih^T + b_ih ; gh = belief @ W_hh^T + b_hh [B,3072] K=1024
//   b1 = GRU(gi, gh, belief)                                  [B,1024]
//   ph = relu(b1 @ W_pb^T + b_pb)                             [B,1024] K=1024
//   prior_raw = ph @ W_ps^T + b_ps                            [B,512]
//   prior sample (softplus(exp(.))+0.1)
//   qh = relu([b1|o_t] @ W_qb^T + b_qb)                       [B,1024] K=2048
//   post_raw = qh @ W_qs^T + b_qs                             [B,512]
//   post sample -> post_states[t] (next carry)
// Carries are read directly from the output buffer slices.
// ---------------------------------------------------------------------------

#define T_STEPS 50
#define BATCH   2048
#define BM 128
#define BN 128
#define BKK 8
#define TM 8
#define TN 8
#define NTHREADS 256

// Scratch (no cudaMalloc allowed)
__device__ float g_rnn[BATCH * 1024];
__device__ float g_gates[(size_t)BATCH * 6144];
__device__ float g_hid[BATCH * 1024];
__device__ float g_head[BATCH * 512];

// C[M,N] = act( [A1|A2](M,K) @ W(N,K)^T + bias ), TN layout (both K-contiguous).
// K1: columns [0,K1) come from A1, [K1,K) from A2. K1 >= K => no concat.
// All dims are multiples of the tile sizes (M=2048, N in {512,1024,3072},
// K in {288,1024,2048}, K1 in {256,1024}) so no bounds checks are needed.
template<int ACT>
__global__ __launch_bounds__(NTHREADS, 2)
void gemm_tn(const float* __restrict__ A1, int lda1, int K1,
             const float* __restrict__ A2, int lda2,
             const float* __restrict__ W, int ldw,
             const float* __restrict__ bias,
             float* __restrict__ C, int ldc, int coloff, int K)
{
    __shared__ float As[2][BKK][BM];
    __shared__ float Bs[2][BKK][BN];

    const int tid  = threadIdx.x;
    const int bm   = blockIdx.y * BM;
    const int bn   = blockIdx.x * BN;
    const int tx   = tid & 15;          // N direction (16)
    const int ty   = tid >> 4;          // M direction (16)
    const int arow = tid >> 1;          // 0..127 (tile row for loads)
    const int ac4  = (tid & 1) << 2;    // 0 or 4 (k sub-column)

    float acc[TM][TN];
    #pragma unroll
    for (int i = 0; i < TM; i++)
        #pragma unroll
        for (int j = 0; j < TN; j++)
            acc[i][j] = 0.0f;

    const int nkt = K / BKK;
    float4 ra, rb;

    // prologue: load tile 0
    {
        int gk = ac4;
        if (gk < K1) ra = *reinterpret_cast<const float4*>(A1 + (size_t)(bm + arow) * lda1 + gk);
        else         ra = *reinterpret_cast<const float4*>(A2 + (size_t)(bm + arow) * lda2 + (gk - K1));
        rb = *reinterpret_cast<const float4*>(W + (size_t)(bn + arow) * ldw + gk);
    }
    As[0][ac4 + 0][arow] = ra.x; As[0][ac4 + 1][arow] = ra.y;
    As[0][ac4 + 2][arow] = ra.z; As[0][ac4 + 3][arow] = ra.w;
    Bs[0][ac4 + 0][arow] = rb.x; Bs[0][ac4 + 1][arow] = rb.y;
    Bs[0][ac4 + 2][arow] = rb.z; Bs[0][ac4 + 3][arow] = rb.w;
    __syncthreads();

    for (int kt = 0; kt < nkt; kt++) {
        const int buf = kt & 1;
        if (kt + 1 < nkt) {
            int gk = (kt + 1) * BKK + ac4;
            if (gk < K1) ra = *reinterpret_cast<const float4*>(A1 + (size_t)(bm + arow) * lda1 + gk);
            else         ra = *reinterpret_cast<const float4*>(A2 + (size_t)(bm + arow) * lda2 + (gk - K1));
            rb = *reinterpret_cast<const float4*>(W + (size_t)(bn + arow) * ldw + (kt + 1) * BKK + ac4);
        }

        #pragma unroll
        for (int kk = 0; kk < BKK; kk++) {
            float a[TM], b[TN];
            *reinterpret_cast<float4*>(&a[0]) = *reinterpret_cast<const float4*>(&As[buf][kk][ty * TM]);
            *reinterpret_cast<float4*>(&a[4]) = *reinterpret_cast<const float4*>(&As[buf][kk][ty * TM + 4]);
            *reinterpret_cast<float4*>(&b[0]) = *reinterpret_cast<const float4*>(&Bs[buf][kk][tx * TN]);
            *reinterpret_cast<float4*>(&b[4]) = *reinterpret_cast<const float4*>(&Bs[buf][kk][tx * TN + 4]);
            #pragma unroll
            for (int i = 0; i < TM; i++)
                #pragma unroll
                for (int j = 0; j < TN; j++)
                    acc[i][j] = fmaf(a[i], b[j], acc[i][j]);
        }

        if (kt + 1 < nkt) {
            const int nb = buf ^ 1;
            As[nb][ac4 + 0][arow] = ra.x; As[nb][ac4 + 1][arow] = ra.y;
            As[nb][ac4 + 2][arow] = ra.z; As[nb][ac4 + 3][arow] = ra.w;
            Bs[nb][ac4 + 0][arow] = rb.x; Bs[nb][ac4 + 1][arow] = rb.y;
            Bs[nb][ac4 + 2][arow] = rb.z; Bs[nb][ac4 + 3][arow] = rb.w;
            __syncthreads();
        }
    }

    // epilogue: bias (+ optional relu), vectorized store
    float bcol[TN];
    #pragma unroll
    for (int j = 0; j < TN; j++) bcol[j] = bias[bn + tx * TN + j];

    #pragma unroll
    for (int i = 0; i < TM; i++) {
        const int m = bm + ty * TM + i;
        float* crow = C + (size_t)m * ldc + coloff + bn + tx * TN;
        #pragma unroll
        for (int j = 0; j < TN; j++) {
            float v = acc[i][j] + bcol[j];
            if (ACT == 1) v = fmaxf(v, 0.0f);
            acc[i][j] = v;
        }
        *reinterpret_cast<float4*>(crow)     = *reinterpret_cast<float4*>(&acc[i][0]);
        *reinterpret_cast<float4*>(crow + 4) = *reinterpret_cast<float4*>(&acc[i][4]);
    }
}

__device__ __forceinline__ float sigmoidf_(float x) { return 1.0f / (1.0f + expf(-x)); }

// gates: [B, 6144] = [ir iz in | hr hz hn], h: [B,1024] prev belief, b1 out
__global__ void gru_kernel(const float* __restrict__ gates,
                           const float* __restrict__ h,
                           float* __restrict__ b1)
{
    int i = blockIdx.x * blockDim.x + threadIdx.x;   // B*1024
    int b = i >> 10, j = i & 1023;
    const float* g = gates + (size_t)b * 6144;
    float ir = g[j],        iz = g[j + 1024], in = g[j + 2048];
    float hr = g[j + 3072], hz = g[j + 4096], hn = g[j + 5120];
    float r = sigmoidf_(ir + hr);
    float z = sigmoidf_(iz + hz);
    float n = tanhf(in + r * hn);
    b1[i] = (1.0f - z) * n + z * h[i];
}

// raw: [B,512] = [mean | log]; std = softplus(exp(log)) + 0.1; s = m + std*noise
__global__ void sample_kernel(const float* __restrict__ raw,
                              const float* __restrict__ noise,
                              float* __restrict__ states,
                              float* __restrict__ means,
                              float* __restrict__ stds)
{
    int i = blockIdx.x * blockDim.x + threadIdx.x;   // B*256
    int b = i >> 8, n = i & 255;
    const float* r = raw + (size_t)b * 512;
    float m  = r[n];
    float x  = expf(r[n + 256]);
    float sp = (x > 20.0f) ? x : log1pf(expf(x));
    float sd = sp + 0.1f;
    states[i] = m + sd * noise[i];
    means[i]  = m;
    stds[i]   = sd;
}

extern "C" void kernel_launch(void* const* d_in, const int* in_sizes, int n_in,
                              void* d_out, int out_size)
{
    (void)in_sizes; (void)n_in; (void)out_size;
    const float* prev_state  = (const float*)d_in[0];   // [B,256]
    const float* actions     = (const float*)d_in[1];   // [T,B,32]
    const float* prev_belief = (const float*)d_in[2];   // [B,1024]
    const float* obs         = (const float*)d_in[3];   // [T,B,1024]
    const float* prior_noise = (const float*)d_in[4];   // [T,B,256]
    const float* post_noise  = (const float*)d_in[5];   // [T,B,256]
    const float* W_sa = (const float*)d_in[6];   const float* b_sa = (const float*)d_in[7];
    const float* W_ih = (const float*)d_in[8];   const float* W_hh = (const float*)d_in[9];
    const float* b_ih = (const float*)d_in[10];  const float* b_hh = (const float*)d_in[11];
    const float* W_pb = (const float*)d_in[12];  const float* b_pb = (const float*)d_in[13];
    const float* W_ps = (const float*)d_in[14];  const float* b_ps = (const float*)d_in[15];
    const float* W_qb = (const float*)d_in[16];  const float* b_qb = (const float*)d_in[17];
    const float* W_qs = (const float*)d_in[18];  const float* b_qs = (const float*)d_in[19];

    float* out = (float*)d_out;
    const size_t TB = (size_t)T_STEPS * BATCH;
    float* beliefs      = out;                         // [T,B,1024]
    float* prior_states = beliefs      + TB * 1024;    // [T,B,256]
    float* prior_means  = prior_states + TB * 256;
    float* prior_stds   = prior_means  + TB * 256;
    float* post_states  = prior_stds   + TB * 256;
    float* post_means   = post_states  + TB * 256;
    float* post_stds    = post_means   + TB * 256;

    float *rnn, *gates, *hid, *head;
    cudaGetSymbolAddress((void**)&rnn,   g_rnn);
    cudaGetSymbolAddress((void**)&gates, g_gates);
    cudaGetSymbolAddress((void**)&hid,   g_hid);
    cudaGetSymbolAddress((void**)&head,  g_head);

    const int NOCAT = 1 << 30;
    const dim3 blk(NTHREADS);
    const dim3 gM(16);  // M blocks = 2048/128
    const dim3 g1024(1024 / BN, 16);
    const dim3 g3072(3072 / BN, 16);
    const dim3 g512 (512  / BN, 16);

    for (int t = 0; t < T_STEPS; t++) {
        const float* state  = (t == 0) ? prev_state  : post_states + (size_t)(t - 1) * BATCH * 256;
        const float* belief = (t == 0) ? prev_belief : beliefs     + (size_t)(t - 1) * BATCH * 1024;
        const float* a_t  = actions + (size_t)t * BATCH * 32;
        const float* o_t  = obs     + (size_t)t * BATCH * 1024;
        float* bel_t = beliefs + (size_t)t * BATCH * 1024;

        // rnn_in = relu([state|a_t] @ W_sa^T + b_sa)
        gemm_tn<1><<<g1024, blk>>>(state, 256, 256, a_t, 32, W_sa, 288, b_sa,
                                   rnn, 1024, 0, 288);
        // gi / gh
        gemm_tn<0><<<g3072, blk>>>(rnn, 1024, NOCAT, nullptr, 0, W_ih, 1024, b_ih,
                                   gates, 6144, 0, 1024);
        gemm_tn<0><<<g3072, blk>>>(belief, 1024, NOCAT, nullptr, 0, W_hh, 1024, b_hh,
                                   gates, 6144, 3072, 1024);
        // GRU -> beliefs[t]
        gru_kernel<<<(BATCH * 1024) / 256, 256>>>(gates, belief, bel_t);

        // prior head
        gemm_tn<1><<<g1024, blk>>>(bel_t, 1024, NOCAT, nullptr, 0, W_pb, 1024, b_pb,
                                   hid, 1024, 0, 1024);
        gemm_tn<0><<<g512, blk>>>(hid, 1024, NOCAT, nullptr, 0, W_ps, 1024, b_ps,
                                  head, 512, 0, 1024);
        sample_kernel<<<(BATCH * 256) / 256, 256>>>(head,
            prior_noise + (size_t)t * BATCH * 256,
            prior_states + (size_t)t * BATCH * 256,
            prior_means  + (size_t)t * BATCH * 256,
            prior_stds   + (size_t)t * BATCH * 256);

        // posterior head
        gemm_tn<1><<<g1024, blk>>>(bel_t, 1024, 1024, o_t, 1024, W_qb, 2048, b_qb,
                                   hid, 1024, 0, 2048);
        gemm_tn<0><<<g512, blk>>>(hid, 1024, NOCAT, nullptr, 0, W_qs, 1024, b_qs,
                                  head, 512, 0, 1024);
        sample_kernel<<<(BATCH * 256) / 256, 256>>>(head,
            post_noise + (size_t)t * BATCH * 256,
            post_states + (size_t)t * BATCH * 256,
            post_means  + (size_t)t * BATCH * 256,
            post_stds   + (size_t)t * BATCH * 256);
    }
}

// round 13
// speedup vs baseline: 3.2274x; 3.2274x over previous
#include <cuda_runtime.h>
#include <math.h>
#include <stdint.h>

// ---------------------------------------------------------------------------
// RSSM scan: T=50, B=2048. GEMMs via mma.sync.m16n8k8 tf32 (base sm_103).
// Precision: split-tf32 everywhere (3 MMAs: lo*hi + hi*lo + hi*hi) — R10
// showed single-tf32 on the prior head alone pushes prior_means to 1.35e-3.
// C[M,N] = act([A1|A2](M,K) @ W(N,K)^T + bias), K-major everywhere.
// BM=BN=128, BK=32, 3-stage cp.async pipeline, 256 thr (8 warps, 2Mx4N),
// warp tile 64x32, ldmatrix fragment loads from XOR-swizzled SMEM.
// ---------------------------------------------------------------------------

#define T_STEPS 50
#define BATCH   2048
#define BK      32
#define STAGES  3

// scratch (no cudaMalloc allowed)
__device__ float g_rnn[BATCH * 1024];
__device__ float g_gates[(size_t)BATCH * 6144];
__device__ float g_hid[BATCH * 1024];
__device__ float g_head[BATCH * 512];

__device__ __forceinline__ uint32_t smem_u32(const void* p) {
    uint32_t a;
    asm("{ .reg .u64 t; cvta.to.shared.u64 t, %1; cvt.u32.u64 %0, t; }" : "=r"(a) : "l"(p));
    return a;
}

__device__ __forceinline__ void cp_async16(uint32_t dst, const void* src) {
    asm volatile("cp.async.cg.shared.global [%0], [%1], 16;" :: "r"(dst), "l"(src));
}
#define CP_COMMIT() asm volatile("cp.async.commit_group;" ::: "memory")

__device__ __forceinline__ void ldsm4(uint32_t& r0, uint32_t& r1, uint32_t& r2, uint32_t& r3,
                                      uint32_t addr) {
    asm volatile("ldmatrix.sync.aligned.m8n8.x4.shared.b16 {%0,%1,%2,%3}, [%4];"
                 : "=r"(r0), "=r"(r1), "=r"(r2), "=r"(r3) : "r"(addr));
}
__device__ __forceinline__ void ldsm2(uint32_t& r0, uint32_t& r1, uint32_t addr) {
    asm volatile("ldmatrix.sync.aligned.m8n8.x2.shared.b16 {%0,%1}, [%2];"
                 : "=r"(r0), "=r"(r1) : "r"(addr));
}

__device__ __forceinline__ void mma_tf32(float* d,
                                         uint32_t a0, uint32_t a1, uint32_t a2, uint32_t a3,
                                         uint32_t b0, uint32_t b1) {
    asm volatile("mma.sync.aligned.m16n8k8.row.col.f32.tf32.tf32.f32 "
                 "{%0,%1,%2,%3}, {%4,%5,%6,%7}, {%8,%9}, {%0,%1,%2,%3};"
                 : "+f"(d[0]), "+f"(d[1]), "+f"(d[2]), "+f"(d[3])
                 : "r"(a0), "r"(a1), "r"(a2), "r"(a3), "r"(b0), "r"(b1));
}

// exact split: hi has tf32-representable mantissa (13 low bits zero), lo exact
__device__ __forceinline__ void split1(uint32_t raw, uint32_t& hi, uint32_t& lo) {
    hi = raw & 0xFFFFE000u;
    lo = __float_as_uint(__uint_as_float(raw) - __uint_as_float(hi));
}

// SMEM: [ bias 512B | stages x (A 16KB) | stages x (B 16KB) ]
#define SM_BIAS 0
#define SM_A    512
#define SM_B    (512 + STAGES * 16384)
#define SM_SIZE (512 + 2 * STAGES * 16384)
// tile row = 32 floats = 128 B = 8 chunks of 16 B; swizzle: chunk ^= (row & 7)

// ---------------------------------------------------------------------------
template<int ACT>
__global__ __launch_bounds__(256)
void gemm_tc(const float* __restrict__ A1, int lda1, int K1,
             const float* __restrict__ A2, int lda2,
             const float* __restrict__ W, int ldw,
             const float* __restrict__ bias,
             float* __restrict__ C, int ldc, int coloff, int K)
{
    extern __shared__ char smem[];
    const uint32_t sb = smem_u32(smem);
    const int tid = threadIdx.x, lane = tid & 31, warp = tid >> 5;
    const int wm = warp & 1, wn = warp >> 1;         // 2 x 4 warp grid
    const int bm = blockIdx.y * 128, bn = blockIdx.x * 128;

    // copy thread mapping: 2 threads per 128B row, 64B each
    const int cr = tid >> 1;                // row 0..127
    const int cc = (tid & 1) * 4;           // chunk base 0 or 4
    const int csw = cr & 7;

    if (tid < 128) reinterpret_cast<float*>(smem + SM_BIAS)[tid] = bias[bn + tid];

    float acc[4][4][4];
    #pragma unroll
    for (int i = 0; i < 4; i++)
        #pragma unroll
        for (int j = 0; j < 4; j++)
            #pragma unroll
            for (int e = 0; e < 4; e++) acc[i][j][e] = 0.0f;

    const int nkt = K / BK;

    auto load_tile = [&](int kt, int buf) {
        const int k0 = kt * BK;
        const float* sA = (k0 < K1)
            ? A1 + (size_t)(bm + cr) * lda1 + k0
            : A2 + (size_t)(bm + cr) * lda2 + (k0 - K1);
        uint32_t dA = sb + SM_A + buf * 16384 + cr * 128;
        #pragma unroll
        for (int c = 0; c < 4; c++)
            cp_async16(dA + (((cc + c) ^ csw) << 4), sA + (cc + c) * 4);
        const float* sB = W + (size_t)(bn + cr) * ldw + k0;
        uint32_t dB = sb + SM_B + buf * 16384 + cr * 128;
        #pragma unroll
        for (int c = 0; c < 4; c++)
            cp_async16(dB + (((cc + c) ^ csw) << 4), sB + (cc + c) * 4);
    };

    #pragma unroll
    for (int s = 0; s < STAGES - 1; s++) {
        if (s < nkt) load_tile(s, s);
        CP_COMMIT();
    }

    // ldmatrix lane addressing
    const int arow_l = lane & 15;     // A x4: rows 0-15 of 16x8 frag
    const int achk_l = lane >> 4;     // chunk half
    const int brow_l = lane & 7;      // B x2: rows 0-7, two k-chunk matrices
    const int bsel_l = (lane >> 3) & 1;

    for (int kt = 0; kt < nkt; kt++) {
        const int buf = kt % STAGES;
        asm volatile("cp.async.wait_group %0;" :: "n"(STAGES - 2) : "memory");
        __syncthreads();

        const int nt = kt + STAGES - 1;
        if (nt < nkt) load_tile(nt, nt % STAGES);
        CP_COMMIT();

        const uint32_t baseA = sb + SM_A + buf * 16384;
        const uint32_t baseB = sb + SM_B + buf * 16384;

        #pragma unroll
        for (int s = 0; s < 4; s++) {           // 4 K=8 steps per BK tile
            uint32_t ahi[4][4], alo[4][4];
            #pragma unroll
            for (int i = 0; i < 4; i++) {
                const int row = wm * 64 + i * 16 + arow_l;
                const int chk = (2 * s + achk_l) ^ (row & 7);
                uint32_t a0, a1, a2, a3;
                ldsm4(a0, a1, a2, a3, baseA + row * 128 + chk * 16);
                split1(a0, ahi[i][0], alo[i][0]);
                split1(a1, ahi[i][1], alo[i][1]);
                split1(a2, ahi[i][2], alo[i][2]);
                split1(a3, ahi[i][3], alo[i][3]);
            }
            #pragma unroll
            for (int j = 0; j < 4; j++) {
                const int row = wn * 32 + j * 8 + brow_l;
                const int chk = (2 * s + bsel_l) ^ (row & 7);
                uint32_t b0, b1;
                ldsm2(b0, b1, baseB + row * 128 + chk * 16);
                uint32_t bh0, bl0, bh1, bl1;
                split1(b0, bh0, bl0);
                split1(b1, bh1, bl1);
                #pragma unroll
                for (int i = 0; i < 4; i++) {
                    mma_tf32(acc[i][j], alo[i][0], alo[i][1], alo[i][2], alo[i][3], bh0, bh1);
                    mma_tf32(acc[i][j], ahi[i][0], ahi[i][1], ahi[i][2], ahi[i][3], bl0, bl1);
                    mma_tf32(acc[i][j], ahi[i][0], ahi[i][1], ahi[i][2], ahi[i][3], bh0, bh1);
                }
            }
        }
        __syncthreads();
    }

    // epilogue: c0,c1 -> (row, col..col+1); c2,c3 -> (row+8, col..col+1)
    const float* biasS = reinterpret_cast<const float*>(smem + SM_BIAS);
    const int er = lane >> 2, ec = (lane & 3) * 2;
    #pragma unroll
    for (int i = 0; i < 4; i++) {
        const int row0 = bm + wm * 64 + i * 16 + er;
        #pragma unroll
        for (int j = 0; j < 4; j++) {
            const int col = wn * 32 + j * 8 + ec;
            float b0 = biasS[col], b1 = biasS[col + 1];
            float2 v0 = make_float2(acc[i][j][0] + b0, acc[i][j][1] + b1);
            float2 v1 = make_float2(acc[i][j][2] + b0, acc[i][j][3] + b1);
            if (ACT == 1) {
                v0.x = fmaxf(v0.x, 0.0f); v0.y = fmaxf(v0.y, 0.0f);
                v1.x = fmaxf(v1.x, 0.0f); v1.y = fmaxf(v1.y, 0.0f);
            }
            *reinterpret_cast<float2*>(C + (size_t)row0 * ldc + coloff + bn + col) = v0;
            *reinterpret_cast<float2*>(C + (size_t)(row0 + 8) * ldc + coloff + bn + col) = v1;
        }
    }
}

// ---------------- elementwise kernels ----------------
__device__ __forceinline__ float sigmoidf_(float x) { return 1.0f / (1.0f + expf(-x)); }

__global__ void gru_kernel(const float* __restrict__ gates,
                           const float* __restrict__ h,
                           float* __restrict__ b1)
{
    int i = blockIdx.x * blockDim.x + threadIdx.x;
    int b = i >> 10, j = i & 1023;
    const float* g = gates + (size_t)b * 6144;
    float ir = g[j],        iz = g[j + 1024], in = g[j + 2048];
    float hr = g[j + 3072], hz = g[j + 4096], hn = g[j + 5120];
    float rr = sigmoidf_(ir + hr);
    float z  = sigmoidf_(iz + hz);
    float n  = tanhf(in + rr * hn);
    b1[i] = (1.0f - z) * n + z * h[i];
}

__global__ void sample_kernel(const float* __restrict__ raw,
                              const float* __restrict__ noise,
                              float* __restrict__ states,
                              float* __restrict__ means,
                              float* __restrict__ stds)
{
    int i = blockIdx.x * blockDim.x + threadIdx.x;
    int b = i >> 8, n = i & 255;
    const float* rp = raw + (size_t)b * 512;
    float m  = rp[n];
    float x  = expf(rp[n + 256]);
    float sp = (x > 20.0f) ? x : log1pf(expf(x));
    float sd = sp + 0.1f;
    states[i] = m + sd * noise[i];
    means[i]  = m;
    stds[i]   = sd;
}

// ---------------------------------------------------------------------------
extern "C" void kernel_launch(void* const* d_in, const int* in_sizes, int n_in,
                              void* d_out, int out_size)
{
    (void)in_sizes; (void)n_in; (void)out_size;
    const float* prev_state  = (const float*)d_in[0];
    const float* actions     = (const float*)d_in[1];
    const float* prev_belief = (const float*)d_in[2];
    const float* obs         = (const float*)d_in[3];
    const float* prior_noise = (const float*)d_in[4];
    const float* post_noise  = (const float*)d_in[5];
    const float* W_sa = (const float*)d_in[6];   const float* b_sa = (const float*)d_in[7];
    const float* W_ih = (const float*)d_in[8];   const float* W_hh = (const float*)d_in[9];
    const float* b_ih = (const float*)d_in[10];  const float* b_hh = (const float*)d_in[11];
    const float* W_pb = (const float*)d_in[12];  const float* b_pb = (const float*)d_in[13];
    const float* W_ps = (const float*)d_in[14];  const float* b_ps = (const float*)d_in[15];
    const float* W_qb = (const float*)d_in[16];  const float* b_qb = (const float*)d_in[17];
    const float* W_qs = (const float*)d_in[18];  const float* b_qs = (const float*)d_in[19];

    float* out = (float*)d_out;
    const size_t TB = (size_t)T_STEPS * BATCH;
    float* beliefs      = out;
    float* prior_states = beliefs      + TB * 1024;
    float* prior_means  = prior_states + TB * 256;
    float* prior_stds   = prior_means  + TB * 256;
    float* post_states  = prior_stds   + TB * 256;
    float* post_means   = post_states  + TB * 256;
    float* post_stds    = post_means   + TB * 256;

    float *rnn, *gates, *hid, *head;
    cudaGetSymbolAddress((void**)&rnn,   g_rnn);
    cudaGetSymbolAddress((void**)&gates, g_gates);
    cudaGetSymbolAddress((void**)&hid,   g_hid);
    cudaGetSymbolAddress((void**)&head,  g_head);

    cudaFuncSetAttribute(gemm_tc<0>, cudaFuncAttributeMaxDynamicSharedMemorySize, SM_SIZE);
    cudaFuncSetAttribute(gemm_tc<1>, cudaFuncAttributeMaxDynamicSharedMemorySize, SM_SIZE);

    const int NOCAT = 1 << 30;
    const dim3 blk(256);
    const dim3 g1024(8, 16), g3072(24, 16), g512(4, 16);

    for (int t = 0; t < T_STEPS; t++) {
        const float* state  = (t == 0) ? prev_state  : post_states + (size_t)(t - 1) * BATCH * 256;
        const float* belief = (t == 0) ? prev_belief : beliefs     + (size_t)(t - 1) * BATCH * 1024;
        const float* a_t = actions + (size_t)t * BATCH * 32;
        const float* o_t = obs     + (size_t)t * BATCH * 1024;
        float* bel_t = beliefs + (size_t)t * BATCH * 1024;

        // rnn_in = relu([state|a_t] @ W_sa^T + b_sa)   K=288, K1=256
        gemm_tc<1><<<g1024, blk, SM_SIZE>>>(state, 256, 256, a_t, 32,
                                            W_sa, 288, b_sa, rnn, 1024, 0, 288);
        // gi = rnn @ W_ih^T ; gh = belief @ W_hh^T
        gemm_tc<0><<<g3072, blk, SM_SIZE>>>(rnn, 1024, NOCAT, nullptr, 0,
                                            W_ih, 1024, b_ih, gates, 6144, 0, 1024);
        gemm_tc<0><<<g3072, blk, SM_SIZE>>>(belief, 1024, NOCAT, nullptr, 0,
                                            W_hh, 1024, b_hh, gates, 6144, 3072, 1024);
        gru_kernel<<<(BATCH * 1024) / 256, 256>>>(gates, belief, bel_t);

        // prior head
        gemm_tc<1><<<g1024, blk, SM_SIZE>>>(bel_t, 1024, NOCAT, nullptr, 0,
                                            W_pb, 1024, b_pb, hid, 1024, 0, 1024);
        gemm_tc<0><<<g512, blk, SM_SIZE>>>(hid, 1024, NOCAT, nullptr, 0,
                                           W_ps, 1024, b_ps, head, 512, 0, 1024);
        sample_kernel<<<(BATCH * 256) / 256, 256>>>(head,
            prior_noise + (size_t)t * BATCH * 256,
            prior_states + (size_t)t * BATCH * 256,
            prior_means  + (size_t)t * BATCH * 256,
            prior_stds   + (size_t)t * BATCH * 256);

        // posterior head: [bel_t | o_t] K=2048, K1=1024
        gemm_tc<1><<<g1024, blk, SM_SIZE>>>(bel_t, 1024, 1024, o_t, 1024,
                                            W_qb, 2048, b_qb, hid, 1024, 0, 2048);
        gemm_tc<0><<<g512, blk, SM_SIZE>>>(hid, 1024, NOCAT, nullptr, 0,
                                           W_qs, 1024, b_qs, head, 512, 0, 1024);
        sample_kernel<<<(BATCH * 256) / 256, 256>>>(head,
            post_noise + (size_t)t * BATCH * 256,
            post_states + (size_t)t * BATCH * 256,
            post_means  + (size_t)t * BATCH * 256,
            post_stds   + (size_t)t * BATCH * 256);
    }
}

// round 14
// speedup vs baseline: 4.9389x; 1.5303x over previous
#include <cuda_runtime.h>
#include <cuda_bf16.h>
#include <math.h>
#include <stdint.h>

// ---------------------------------------------------------------------------
// RSSM scan: T=50, B=2048. GEMMs via mma.sync.m16n8k16 bf16 (base sm_103).
// Precision: every operand pre-split into bf16 hi/lo planes (hi=rn(v),
// lo=rn(v-hi)); each GEMM computes hi*hi + lo*hi + hi*lo (3 MMAs per K16 —
// half the MMA instructions of the R13 split-tf32 scheme at K8).
// C[M,N] = act([A1|A2](M,K) @ W(N,K)^T + bias), K-major everywhere.
// BM=BN=128, BK=64, 3-stage cp.async pipe, 256 thr (8 warps, 2Mx4N),
// warp tile 64x32, ldmatrix.b16 fragment loads from XOR-swizzled SMEM.
// ---------------------------------------------------------------------------

#define T_STEPS 50
#define BATCH   2048
#define BK      64
#define STAGES  3

typedef __nv_bfloat16 bf16;

// ---------------- scratch (no cudaMalloc allowed) ----------------
__device__ bf16 WsaH[1024 * 320],  WsaL[1024 * 320];
__device__ bf16 WihH[3072 * 1024], WihL[3072 * 1024];
__device__ bf16 WhhH[3072 * 1024], WhhL[3072 * 1024];
__device__ bf16 WpbH[1024 * 1024], WpbL[1024 * 1024];
__device__ bf16 WpsH[512 * 1024],  WpsL[512 * 1024];
__device__ bf16 WqbH[(size_t)1024 * 2048], WqbL[(size_t)1024 * 2048];
__device__ bf16 WqsH[512 * 1024],  WqsL[512 * 1024];
__device__ bf16 actPH[(size_t)T_STEPS * BATCH * 64], actPL[(size_t)T_STEPS * BATCH * 64];
__device__ bf16 statePH[BATCH * 256],  statePL[BATCH * 256];
__device__ bf16 belPH[BATCH * 1024],   belPL[BATCH * 1024];
__device__ bf16 rnnPH[BATCH * 1024],   rnnPL[BATCH * 1024];
__device__ bf16 hidPH[BATCH * 1024],   hidPL[BATCH * 1024];
__device__ bf16 obsPH[BATCH * 1024],   obsPL[BATCH * 1024];
__device__ float g_gates[(size_t)BATCH * 6144];
__device__ float g_head[BATCH * 512];

// ---------------- helpers ----------------
__device__ __forceinline__ uint32_t smem_u32(const void* p) {
    uint32_t a;
    asm("{ .reg .u64 t; cvta.to.shared.u64 t, %1; cvt.u32.u64 %0, t; }" : "=r"(a) : "l"(p));
    return a;
}
__device__ __forceinline__ void cp_async16(uint32_t dst, const void* src) {
    asm volatile("cp.async.cg.shared.global [%0], [%1], 16;" :: "r"(dst), "l"(src));
}
#define CP_COMMIT() asm volatile("cp.async.commit_group;" ::: "memory")

__device__ __forceinline__ void ldsm4(uint32_t& r0, uint32_t& r1, uint32_t& r2, uint32_t& r3,
                                      uint32_t addr) {
    asm volatile("ldmatrix.sync.aligned.m8n8.x4.shared.b16 {%0,%1,%2,%3}, [%4];"
                 : "=r"(r0), "=r"(r1), "=r"(r2), "=r"(r3) : "r"(addr));
}
__device__ __forceinline__ void mma_bf16(float* d,
                                         uint32_t a0, uint32_t a1, uint32_t a2, uint32_t a3,
                                         uint32_t b0, uint32_t b1) {
    asm volatile("mma.sync.aligned.m16n8k16.row.col.f32.bf16.bf16.f32 "
                 "{%0,%1,%2,%3}, {%4,%5,%6,%7}, {%8,%9}, {%0,%1,%2,%3};"
                 : "+f"(d[0]), "+f"(d[1]), "+f"(d[2]), "+f"(d[3])
                 : "r"(a0), "r"(a1), "r"(a2), "r"(a3), "r"(b0), "r"(b1));
}
__device__ __forceinline__ void split_bf(float v, bf16& h, bf16& l) {
    h = __float2bfloat16_rn(v);
    l = __float2bfloat16_rn(v - __bfloat162float(h));
}
__device__ __forceinline__ uint32_t pack2(bf16 x, bf16 y) {
    return ((uint32_t)__bfloat16_as_ushort(y) << 16) | __bfloat16_as_ushort(x);
}

// SMEM: [bias 512B | stage0: Ahi Alo Bhi Blo (4x16KB) | stage1 | stage2]
#define SM_BIAS 0
#define SM_TILE 512
#define STG_SZ  65536
#define PL_SZ   16384
#define SM_SIZE (512 + STAGES * STG_SZ)

// ---------------------------------------------------------------------------
// OUTP=0: write fp32 C.  OUTP=1: write bf16 hi/lo planes (Ch/Cl).
template<int ACT, int OUTP>
__global__ __launch_bounds__(256)
void gemm_bf(const bf16* __restrict__ A1h, const bf16* __restrict__ A1l, int lda1, int K1,
             const bf16* __restrict__ A2h, const bf16* __restrict__ A2l, int lda2,
             const bf16* __restrict__ Wh,  const bf16* __restrict__ Wl,  int ldw,
             const float* __restrict__ bias,
             float* __restrict__ C, bf16* __restrict__ Ch, bf16* __restrict__ Cl,
             int ldc, int coloff, int K)
{
    extern __shared__ char smem[];
    const uint32_t sb = smem_u32(smem);
    const int tid = threadIdx.x, lane = tid & 31, warp = tid >> 5;
    const int wm = warp & 1, wn = warp >> 1;          // 2 x 4 warp grid
    const int bm = blockIdx.y * 128, bn = blockIdx.x * 128;

    // copy mapping: 2 threads per 128B row (64 bf16), 4 chunks of 16B each
    const int cr = tid >> 1;
    const int ch0 = (tid & 1) * 4;
    const int csw = cr & 7;

    if (tid < 128) reinterpret_cast<float*>(smem + SM_BIAS)[tid] = bias[bn + tid];

    float acc[4][4][4];
    #pragma unroll
    for (int i = 0; i < 4; i++)
        #pragma unroll
        for (int j = 0; j < 4; j++)
            #pragma unroll
            for (int e = 0; e < 4; e++) acc[i][j][e] = 0.0f;

    const int nkt = K / BK;

    auto load_tile = [&](int kt, int buf) {
        const int k0 = kt * BK;
        const bf16 *sah, *sal;
        if (k0 < K1) {
            sah = A1h + (size_t)(bm + cr) * lda1 + k0;
            sal = A1l + (size_t)(bm + cr) * lda1 + k0;
        } else {
            sah = A2h + (size_t)(bm + cr) * lda2 + (k0 - K1);
            sal = A2l + (size_t)(bm + cr) * lda2 + (k0 - K1);
        }
        const bf16* swh = Wh + (size_t)(bn + cr) * ldw + k0;
        const bf16* swl = Wl + (size_t)(bn + cr) * ldw + k0;
        const uint32_t st = sb + SM_TILE + buf * STG_SZ;
        uint32_t dA = st + cr * 128;
        #pragma unroll
        for (int c = 0; c < 4; c++) {
            const int ci = ch0 + c;
            const uint32_t off = ((ci ^ csw) << 4) ;
            cp_async16(dA + off,              sah + ci * 8);
            cp_async16(dA + PL_SZ + off,      sal + ci * 8);
            cp_async16(dA + 2 * PL_SZ + off,  swh + ci * 8);
            cp_async16(dA + 3 * PL_SZ + off,  swl + ci * 8);
        }
    };

    #pragma unroll
    for (int s = 0; s < STAGES - 1; s++) {
        if (s < nkt) load_tile(s, s);
        CP_COMMIT();
    }

    // ldmatrix lane addressing
    const int arow_l = lane & 15;                 // A rows (mats 0/1)
    const int achk_l = lane >> 4;                 // +1 chunk for mats 2/3 (k+8)
    const int brow_l = (lane & 7) + ((lane & 16) ? 8 : 0);  // B rows: j even/odd
    const int bchk_l = (lane >> 3) & 1;           // k chunk (b0 / b1)

    for (int kt = 0; kt < nkt; kt++) {
        const int buf = kt % STAGES;
        asm volatile("cp.async.wait_group %0;" :: "n"(STAGES - 2) : "memory");
        __syncthreads();

        const int nt = kt + STAGES - 1;
        if (nt < nkt) load_tile(nt, nt % STAGES);
        CP_COMMIT();

        const uint32_t st = sb + SM_TILE + buf * STG_SZ;

        #pragma unroll
        for (int s = 0; s < 4; s++) {            // 4 K16 steps per BK=64 tile
            uint32_t ahi[4][4], alo[4][4];
            #pragma unroll
            for (int i = 0; i < 4; i++) {
                const int row = wm * 64 + i * 16 + arow_l;
                const int chk = (2 * s + achk_l) ^ (row & 7);
                ldsm4(ahi[i][0], ahi[i][1], ahi[i][2], ahi[i][3],
                      st + row * 128 + chk * 16);
                ldsm4(alo[i][0], alo[i][1], alo[i][2], alo[i][3],
                      st + PL_SZ + row * 128 + chk * 16);
            }
            #pragma unroll
            for (int j2 = 0; j2 < 2; j2++) {     // two N=16 groups (j pairs)
                const int row = wn * 32 + j2 * 16 + brow_l;
                const int chk = (2 * s + bchk_l) ^ (row & 7);
                uint32_t bh[4], bl[4];
                ldsm4(bh[0], bh[1], bh[2], bh[3], st + 2 * PL_SZ + row * 128 + chk * 16);
                ldsm4(bl[0], bl[1], bl[2], bl[3], st + 3 * PL_SZ + row * 128 + chk * 16);
                #pragma unroll
                for (int jo = 0; jo < 2; jo++) {
                    const int j = 2 * j2 + jo;
                    #pragma unroll
                    for (int i = 0; i < 4; i++) {
                        mma_bf16(acc[i][j], alo[i][0], alo[i][1], alo[i][2], alo[i][3],
                                 bh[2 * jo], bh[2 * jo + 1]);
                        mma_bf16(acc[i][j], ahi[i][0], ahi[i][1], ahi[i][2], ahi[i][3],
                                 bl[2 * jo], bl[2 * jo + 1]);
                        mma_bf16(acc[i][j], ahi[i][0], ahi[i][1], ahi[i][2], ahi[i][3],
                                 bh[2 * jo], bh[2 * jo + 1]);
                    }
                }
            }
        }
        __syncthreads();
    }

    // epilogue
    const float* biasS = reinterpret_cast<const float*>(smem + SM_BIAS);
    const int er = lane >> 2, ec = (lane & 3) * 2;
    #pragma unroll
    for (int i = 0; i < 4; i++) {
        const int row0 = bm + wm * 64 + i * 16 + er;
        #pragma unroll
        for (int j = 0; j < 4; j++) {
            const int col = wn * 32 + j * 8 + ec;
            float b0 = biasS[col], b1 = biasS[col + 1];
            float v0x = acc[i][j][0] + b0, v0y = acc[i][j][1] + b1;
            float v1x = acc[i][j][2] + b0, v1y = acc[i][j][3] + b1;
            if (ACT == 1) {
                v0x = fmaxf(v0x, 0.0f); v0y = fmaxf(v0y, 0.0f);
                v1x = fmaxf(v1x, 0.0f); v1y = fmaxf(v1y, 0.0f);
            }
            if (OUTP == 0) {
                *reinterpret_cast<float2*>(C + (size_t)row0 * ldc + coloff + bn + col) =
                    make_float2(v0x, v0y);
                *reinterpret_cast<float2*>(C + (size_t)(row0 + 8) * ldc + coloff + bn + col) =
                    make_float2(v1x, v1y);
            } else {
                bf16 hx, lx, hy, ly;
                split_bf(v0x, hx, lx); split_bf(v0y, hy, ly);
                *reinterpret_cast<uint32_t*>(Ch + (size_t)row0 * ldc + bn + col) = pack2(hx, hy);
                *reinterpret_cast<uint32_t*>(Cl + (size_t)row0 * ldc + bn + col) = pack2(lx, ly);
                split_bf(v1x, hx, lx); split_bf(v1y, hy, ly);
                *reinterpret_cast<uint32_t*>(Ch + (size_t)(row0 + 8) * ldc + bn + col) = pack2(hx, hy);
                *reinterpret_cast<uint32_t*>(Cl + (size_t)(row0 + 8) * ldc + bn + col) = pack2(lx, ly);
            }
        }
    }
}

// ---------------- conversion: fp32 [R x Ks] -> bf16 planes [R x Kd], zero-pad
__global__ void split_pad(const float* __restrict__ src,
                          bf16* __restrict__ hi, bf16* __restrict__ lo,
                          int Ks, int Kd, int total)
{
    int idx = blockIdx.x * blockDim.x + threadIdx.x;
    if (idx >= total) return;
    int r = idx / Kd, k = idx - r * Kd;
    float v = (k < Ks) ? src[(size_t)r * Ks + k] : 0.0f;
    bf16 h, l;
    split_bf(v, h, l);
    hi[idx] = h; lo[idx] = l;
}

// ---------------- elementwise kernels ----------------
__device__ __forceinline__ float sigmoidf_(float x) { return 1.0f / (1.0f + expf(-x)); }

__global__ void gru_kernel(const float* __restrict__ gates,
                           const float* __restrict__ h,
                           float* __restrict__ b1,
                           bf16* __restrict__ pH, bf16* __restrict__ pL)
{
    int i = blockIdx.x * blockDim.x + threadIdx.x;
    int b = i >> 10, j = i & 1023;
    const float* g = gates + (size_t)b * 6144;
    float ir = g[j],        iz = g[j + 1024], in = g[j + 2048];
    float hr = g[j + 3072], hz = g[j + 4096], hn = g[j + 5120];
    float rr = sigmoidf_(ir + hr);
    float z  = sigmoidf_(iz + hz);
    float n  = tanhf(in + rr * hn);
    float v  = (1.0f - z) * n + z * h[i];
    b1[i] = v;
    bf16 hh, ll; split_bf(v, hh, ll);
    pH[i] = hh; pL[i] = ll;
}

template<int PLANES>
__global__ void sample_kernel(const float* __restrict__ raw,
                              const float* __restrict__ noise,
                              float* __restrict__ states,
                              float* __restrict__ means,
                              float* __restrict__ stds,
                              bf16* __restrict__ pH, bf16* __restrict__ pL)
{
    int i = blockIdx.x * blockDim.x + threadIdx.x;
    int b = i >> 8, n = i & 255;
    const float* rp = raw + (size_t)b * 512;
    float m  = rp[n];
    float x  = expf(rp[n + 256]);
    float sp = (x > 20.0f) ? x : log1pf(expf(x));
    float sd = sp + 0.1f;
    float s  = m + sd * noise[i];
    states[i] = s;
    means[i]  = m;
    stds[i]   = sd;
    if (PLANES) {
        bf16 hh, ll; split_bf(s, hh, ll);
        pH[i] = hh; pL[i] = ll;
    }
}

// ---------------------------------------------------------------------------
extern "C" void kernel_launch(void* const* d_in, const int* in_sizes, int n_in,
                              void* d_out, int out_size)
{
    (void)in_sizes; (void)n_in; (void)out_size;
    const float* prev_state  = (const float*)d_in[0];
    const float* actions     = (const float*)d_in[1];
    const float* prev_belief = (const float*)d_in[2];
    const float* obs         = (const float*)d_in[3];
    const float* prior_noise = (const float*)d_in[4];
    const float* post_noise  = (const float*)d_in[5];
    const float* W_sa = (const float*)d_in[6];   const float* b_sa = (const float*)d_in[7];
    const float* W_ih = (const float*)d_in[8];   const float* W_hh = (const float*)d_in[9];
    const float* b_ih = (const float*)d_in[10];  const float* b_hh = (const float*)d_in[11];
    const float* W_pb = (const float*)d_in[12];  const float* b_pb = (const float*)d_in[13];
    const float* W_ps = (const float*)d_in[14];  const float* b_ps = (const float*)d_in[15];
    const float* W_qb = (const float*)d_in[16];  const float* b_qb = (const float*)d_in[17];
    const float* W_qs = (const float*)d_in[18];  const float* b_qs = (const float*)d_in[19];

    float* out = (float*)d_out;
    const size_t TB = (size_t)T_STEPS * BATCH;
    float* beliefs      = out;
    float* prior_states = beliefs      + TB * 1024;
    float* prior_means  = prior_states + TB * 256;
    float* prior_stds   = prior_means  + TB * 256;
    float* post_states  = prior_stds   + TB * 256;
    float* post_means   = post_states  + TB * 256;
    float* post_stds    = post_means   + TB * 256;

    // scratch symbol addresses
    bf16 *wsaH, *wsaL, *wihH, *wihL, *whhH, *whhL, *wpbH, *wpbL,
         *wpsH, *wpsL, *wqbH, *wqbL, *wqsH, *wqsL,
         *actH, *actL, *stH, *stL, *beH, *beL, *rnH, *rnL, *hiH, *hiL, *obH, *obL;
    float *gates, *head;
    cudaGetSymbolAddress((void**)&wsaH, WsaH); cudaGetSymbolAddress((void**)&wsaL, WsaL);
    cudaGetSymbolAddress((void**)&wihH, WihH); cudaGetSymbolAddress((void**)&wihL, WihL);
    cudaGetSymbolAddress((void**)&whhH, WhhH); cudaGetSymbolAddress((void**)&whhL, WhhL);
    cudaGetSymbolAddress((void**)&wpbH, WpbH); cudaGetSymbolAddress((void**)&wpbL, WpbL);
    cudaGetSymbolAddress((void**)&wpsH, WpsH); cudaGetSymbolAddress((void**)&wpsL, WpsL);
    cudaGetSymbolAddress((void**)&wqbH, WqbH); cudaGetSymbolAddress((void**)&wqbL, WqbL);
    cudaGetSymbolAddress((void**)&wqsH, WqsH); cudaGetSymbolAddress((void**)&wqsL, WqsL);
    cudaGetSymbolAddress((void**)&actH, actPH); cudaGetSymbolAddress((void**)&actL, actPL);
    cudaGetSymbolAddress((void**)&stH, statePH); cudaGetSymbolAddress((void**)&stL, statePL);
    cudaGetSymbolAddress((void**)&beH, belPH);   cudaGetSymbolAddress((void**)&beL, belPL);
    cudaGetSymbolAddress((void**)&rnH, rnnPH);   cudaGetSymbolAddress((void**)&rnL, rnnPL);
    cudaGetSymbolAddress((void**)&hiH, hidPH);   cudaGetSymbolAddress((void**)&hiL, hidPL);
    cudaGetSymbolAddress((void**)&obH, obsPH);   cudaGetSymbolAddress((void**)&obL, obsPL);
    cudaGetSymbolAddress((void**)&gates, g_gates);
    cudaGetSymbolAddress((void**)&head,  g_head);

    cudaFuncSetAttribute(gemm_bf<0, 0>, cudaFuncAttributeMaxDynamicSharedMemorySize, SM_SIZE);
    cudaFuncSetAttribute(gemm_bf<1, 1>, cudaFuncAttributeMaxDynamicSharedMemorySize, SM_SIZE);

    auto conv = [&](const float* s, bf16* h, bf16* l, int R, int Ks, int Kd) {
        int tot = R * Kd;
        split_pad<<<(tot + 255) / 256, 256>>>(s, h, l, Ks, Kd, tot);
    };

    // one-time conversions (per launch; deterministic)
    conv(W_sa, wsaH, wsaL, 1024, 288, 320);
    conv(W_ih, wihH, wihL, 3072, 1024, 1024);
    conv(W_hh, whhH, whhL, 3072, 1024, 1024);
    conv(W_pb, wpbH, wpbL, 1024, 1024, 1024);
    conv(W_ps, wpsH, wpsL, 512, 1024, 1024);
    conv(W_qb, wqbH, wqbL, 1024, 2048, 2048);
    conv(W_qs, wqsH, wqsL, 512, 1024, 1024);
    conv(actions, actH, actL, T_STEPS * BATCH, 32, 64);
    conv(prev_state, stH, stL, BATCH, 256, 256);
    conv(prev_belief, beH, beL, BATCH, 1024, 1024);

    const int NOCAT = 1 << 30;
    const dim3 blk(256);
    const dim3 g1024(8, 16), g3072(24, 16), g512(4, 16);

    for (int t = 0; t < T_STEPS; t++) {
        const float* h_prev = (t == 0) ? prev_belief : beliefs + (size_t)(t - 1) * BATCH * 1024;
        float* bel_t = beliefs + (size_t)t * BATCH * 1024;

        // rnn = relu([state|a_t] @ W_sa^T + b_sa)  K=320 (padded), K1=256 -> planes
        gemm_bf<1, 1><<<g1024, blk, SM_SIZE>>>(
            stH, stL, 256, 256,
            actH + (size_t)t * BATCH * 64, actL + (size_t)t * BATCH * 64, 64,
            wsaH, wsaL, 320, b_sa, nullptr, rnH, rnL, 1024, 0, 320);
        // gi / gh -> fp32 gates
        gemm_bf<0, 0><<<g3072, blk, SM_SIZE>>>(
            rnH, rnL, 1024, NOCAT, nullptr, nullptr, 0,
            wihH, wihL, 1024, b_ih, gates, nullptr, nullptr, 6144, 0, 1024);
        gemm_bf<0, 0><<<g3072, blk, SM_SIZE>>>(
            beH, beL, 1024, NOCAT, nullptr, nullptr, 0,
            whhH, whhL, 1024, b_hh, gates, nullptr, nullptr, 6144, 3072, 1024);
        // GRU -> beliefs[t] fp32 + belief planes
        gru_kernel<<<(BATCH * 1024) / 256, 256>>>(gates, h_prev, bel_t, beH, beL);

        // prior head
        gemm_bf<1, 1><<<g1024, blk, SM_SIZE>>>(
            beH, beL, 1024, NOCAT, nullptr, nullptr, 0,
            wpbH, wpbL, 1024, b_pb, nullptr, hiH, hiL, 1024, 0, 1024);
        gemm_bf<0, 0><<<g512, blk, SM_SIZE>>>(
            hiH, hiL, 1024, NOCAT, nullptr, nullptr, 0,
            wpsH, wpsL, 1024, b_ps, head, nullptr, nullptr, 512, 0, 1024);
        sample_kernel<0><<<(BATCH * 256) / 256, 256>>>(head,
            prior_noise + (size_t)t * BATCH * 256,
            prior_states + (size_t)t * BATCH * 256,
            prior_means  + (size_t)t * BATCH * 256,
            prior_stds   + (size_t)t * BATCH * 256, nullptr, nullptr);

        // posterior head: convert obs_t, then [bel|obs] K=2048, K1=1024
        conv(obs + (size_t)t * BATCH * 1024, obH, obL, BATCH, 1024, 1024);
        gemm_bf<1, 1><<<g1024, blk, SM_SIZE>>>(
            beH, beL, 1024, 1024, obH, obL, 1024,
            wqbH, wqbL, 2048, b_qb, nullptr, hiH, hiL, 1024, 0, 2048);
        gemm_bf<0, 0><<<g512, blk, SM_SIZE>>>(
            hiH, hiL, 1024, NOCAT, nullptr, nullptr, 0,
            wqsH, wqsL, 1024, b_qs, head, nullptr, nullptr, 512, 0, 1024);
        sample_kernel<1><<<(BATCH * 256) / 256, 256>>>(head,
            post_noise + (size_t)t * BATCH * 256,
            post_states + (size_t)t * BATCH * 256,
            post_means  + (size_t)t * BATCH * 256,
            post_stds   + (size_t)t * BATCH * 256, stH, stL);
    }
}